// round 7
// baseline (speedup 1.0000x reference)
#include <cuda_runtime.h>
#include <cuda_fp16.h>
#include <cstdint>
#include <cstddef>

// out = x[1024,65536] @ W2[2048,65536]^T, W2[o,l*32+c]=W_pos[o,l]*W_chan[o,c].
// fp16 operands / fp32 accum via mma.sync.m16n8k16. B (=W2) tile generated on
// the fly, pipelined ONE ITERATION AHEAD so gen overlaps MMA (1 sync/iter).
// CTA 128x128x128, 16 warps (warp 32x32), 3-stage cp.async A/Wp, 2 B buffers.

static constexpr int MB = 1024, NO = 2048, LL = 2048, CC = 32;
static constexpr int KK = LL * CC;                  // 65536

__device__ __half g_xh[(size_t)MB * KK];            // fp16 A

__device__ __forceinline__ uint32_t pk(float a, float b) {
    __half2 h = __floats2half2_rn(a, b);
    return *reinterpret_cast<uint32_t*>(&h);
}

__global__ void k_convert(const float4* __restrict__ x4) {
    int i = blockIdx.x * 256 + threadIdx.x;
    float4 v = x4[i];
    uint2 u; u.x = pk(v.x, v.y); u.y = pk(v.z, v.w);
    reinterpret_cast<uint2*>(g_xh)[i] = u;
}

__device__ __forceinline__ uint32_t smem_u32(const void* p) {
    uint32_t a;
    asm("{ .reg .u64 t; cvta.to.shared.u64 t, %1; cvt.u32.u64 %0, t; }" : "=r"(a) : "l"(p));
    return a;
}
__device__ __forceinline__ void cpa16(uint32_t s, const void* g) {
    asm volatile("cp.async.cg.shared.global [%0], [%1], 16;" :: "r"(s), "l"(g) : "memory");
}
#define CP_COMMIT() asm volatile("cp.async.commit_group;" ::: "memory")
#define CP_WAIT(n)  asm volatile("cp.async.wait_group %0;" :: "n"(n) : "memory")

__device__ __forceinline__ void ldsm4(uint32_t* r, uint32_t a) {
    asm volatile("ldmatrix.sync.aligned.m8n8.x4.shared.b16 {%0,%1,%2,%3}, [%4];"
                 : "=r"(r[0]), "=r"(r[1]), "=r"(r[2]), "=r"(r[3]) : "r"(a));
}
__device__ __forceinline__ void mma16816(float* c, const uint32_t* a,
                                         uint32_t b0, uint32_t b1) {
    asm volatile("mma.sync.aligned.m16n8k16.row.col.f32.f16.f16.f32 "
                 "{%0,%1,%2,%3}, {%4,%5,%6,%7}, {%8,%9}, {%0,%1,%2,%3};"
                 : "+f"(c[0]), "+f"(c[1]), "+f"(c[2]), "+f"(c[3])
                 : "r"(a[0]), "r"(a[1]), "r"(a[2]), "r"(a[3]), "r"(b0), "r"(b1));
}

static constexpr int BM = 128, BN = 128, KT = 128;
static constexpr int NIT = KK / KT;                 // 512
// smem layout (bytes)
static constexpr uint32_t WP_OFF = 0;               // Wp stages: 3 x 2KB
static constexpr uint32_t WP_STG = 2048;
static constexpr uint32_t A_OFF  = 6144;            // A stages: 3 x 32KB (256B rows)
static constexpr uint32_t A_STG  = 32768;
static constexpr uint32_t B_OFF  = 104448;          // B bufs:   2 x 32KB (256B rows)
static constexpr uint32_t B_STG  = 32768;
static constexpr uint32_t SMEM_BYTES = 169984;

// 16B-chunk swizzle for 256B rows: XOR within each 128B half
__device__ __forceinline__ uint32_t swz(uint32_t chk, uint32_t row) {
    return (chk & 8u) | ((chk & 7u) ^ (row & 7u));
}

__global__ void __launch_bounds__(512, 1) k_gemm(float* __restrict__ out,
                                                 const float* __restrict__ Wp,
                                                 const float* __restrict__ Wc) {
    extern __shared__ char smem[];
    const uint32_t sb = smem_u32(smem);
    const int t = threadIdx.x;
    const int w = t >> 5, l = t & 31;
    const int m0 = blockIdx.y * BM, n0 = blockIdx.x * BN;
    const int wm = (w >> 2) * 32, wn = (w & 3) * 32;   // 4x4 warp grid, warp 32x32

    // ---- B-gen geometry + Wc hoisted to registers (read gmem once) ----
    const int go = t >> 2, gs = t & 3;                 // o-row, 8-channel group
    float wcr[8];
    {
        const float4* wcg = reinterpret_cast<const float4*>(
            Wc + (size_t)(n0 + go) * CC + gs * 8);
        float4 w0 = wcg[0], w1 = wcg[1];
        wcr[0] = w0.x; wcr[1] = w0.y; wcr[2] = w0.z; wcr[3] = w0.w;
        wcr[4] = w1.x; wcr[5] = w1.y; wcr[6] = w1.z; wcr[7] = w1.w;
    }

    // ---- A loader geometry ----
    const int ar = t >> 2, aq = t & 3;
    const __half* gA = g_xh + (size_t)(m0 + ar) * KK;
    const uint32_t arx = (uint32_t)(ar & 7);

    auto load_stage = [&](int it, int slot) {
        const uint32_t ab = sb + A_OFF + (uint32_t)slot * A_STG + (uint32_t)ar * 256u;
        const __half* ga = gA + (size_t)it * KT;
#pragma unroll
        for (int i = 0; i < 4; ++i) {
            const uint32_t c = (uint32_t)(aq + 4 * i);
            cpa16(ab + (swz(c, arx) * 16u), ga + c * 8);
        }
        if (t < 128) {
            cpa16(sb + WP_OFF + (uint32_t)slot * WP_STG + (uint32_t)t * 16u,
                  Wp + (size_t)(n0 + t) * LL + (size_t)it * 4);
        }
    };

    // gen W2 tile for k-slice kt into buffer buf, reading Wp from slot
    auto gen_b = [&](int slot, int buf) {
        const float4 wp4 = *reinterpret_cast<const float4*>(
            smem + WP_OFF + (uint32_t)slot * WP_STG + go * 16);
        char* brow = smem + B_OFF + (uint32_t)buf * B_STG + go * 256;
        const float wpv[4] = {wp4.x, wp4.y, wp4.z, wp4.w};
#pragma unroll
        for (int lp = 0; lp < 4; ++lp) {
            const float wpf = wpv[lp];
            uint4 u;
            u.x = pk(wpf * wcr[0], wpf * wcr[1]);
            u.y = pk(wpf * wcr[2], wpf * wcr[3]);
            u.z = pk(wpf * wcr[4], wpf * wcr[5]);
            u.w = pk(wpf * wcr[6], wpf * wcr[7]);
            const uint32_t chk = (uint32_t)(lp * 4 + gs);
            *reinterpret_cast<uint4*>(brow + swz(chk, (uint32_t)go) * 16u) = u;
        }
    };

    float acc[2][4][4];
#pragma unroll
    for (int i = 0; i < 2; ++i)
#pragma unroll
        for (int j = 0; j < 4; ++j)
#pragma unroll
            for (int k = 0; k < 4; ++k) acc[i][j][k] = 0.f;

    // prologue: stages 0,1 in flight; gen B0 after stage 0 lands
    load_stage(0, 0); CP_COMMIT();
    load_stage(1, 1); CP_COMMIT();
    CP_WAIT(1);
    __syncthreads();          // A0, Wp0 visible
    gen_b(0, 0);              // B0 (published by first in-loop sync)

    // ldmatrix lane geometry (verified R3-R6)
    const int arow_i = (l & 7) + ((l >> 3) & 1) * 8, achk_i = (l >> 4);
    const int brow_i = (l & 7) + ((l >> 4) << 3),   bchk_i = (l >> 3) & 1;

    uint32_t af[2][2][4], bf[2][2][4];

    int slotC = 0, slotG = 1, slotP = 2;    // A/Wp slots: consume, gen-src, load-dst
    for (int it = 0; it < NIT; ++it) {
        CP_WAIT(0);           // A[it+1], Wp[it+1] arrived
        __syncthreads();      // publish B[it] (gen'd last iter) + A[it+1]/Wp[it+1]

        if (it + 2 < NIT) { load_stage(it + 2, slotP); CP_COMMIT(); }
        if (it + 1 < NIT) gen_b(slotG, (it + 1) & 1);   // overlaps with MMA below

        const uint32_t ast = sb + A_OFF + (uint32_t)slotC * A_STG;
        const uint32_t bst = sb + B_OFF + (uint32_t)(it & 1) * B_STG;

        auto load_frags = [&](int ks, int buf) {
#pragma unroll
            for (int mi = 0; mi < 2; ++mi) {
                const uint32_t row = (uint32_t)(wm + mi * 16 + arow_i);
                const uint32_t chk = (uint32_t)(achk_i + ks * 2);
                ldsm4(af[buf][mi], ast + row * 256u + swz(chk, row) * 16u);
            }
#pragma unroll
            for (int nj = 0; nj < 2; ++nj) {
                const uint32_t row = (uint32_t)(wn + nj * 16 + brow_i);
                const uint32_t chk = (uint32_t)(bchk_i + ks * 2);
                ldsm4(bf[buf][nj], bst + row * 256u + swz(chk, row) * 16u);
            }
        };

        load_frags(0, 0);
#pragma unroll
        for (int ks = 0; ks < KT / 16; ++ks) {
            if (ks + 1 < KT / 16) load_frags(ks + 1, (ks + 1) & 1);
            const int bu = ks & 1;
#pragma unroll
            for (int mi = 0; mi < 2; ++mi)
#pragma unroll
                for (int j = 0; j < 4; ++j)
                    mma16816(acc[mi][j], af[bu][mi],
                             bf[bu][j >> 1][(j & 1) * 2], bf[bu][j >> 1][(j & 1) * 2 + 1]);
        }

        const int tmp = slotC;
        slotC = slotG; slotG = slotP; slotP = tmp;
    }

#pragma unroll
    for (int mi = 0; mi < 2; ++mi) {
        const int row = m0 + wm + mi * 16 + (l >> 2);
#pragma unroll
        for (int j = 0; j < 4; ++j) {
            const int col = n0 + wn + j * 8 + (l & 3) * 2;
            float2 lo; lo.x = acc[mi][j][0]; lo.y = acc[mi][j][1];
            float2 hi; hi.x = acc[mi][j][2]; hi.y = acc[mi][j][3];
            *reinterpret_cast<float2*>(out + (size_t)row * NO + col) = lo;
            *reinterpret_cast<float2*>(out + (size_t)(row + 8) * NO + col) = hi;
        }
    }
}

extern "C" void kernel_launch(void* const* d_in, const int* in_sizes, int n_in,
                              void* d_out, int out_size) {
    (void)in_sizes; (void)n_in; (void)out_size;
    const float* x  = (const float*)d_in[0];
    const float* Wp = (const float*)d_in[1];
    const float* Wc = (const float*)d_in[2];
    float* out = (float*)d_out;

    k_convert<<<(MB * (KK / 4)) / 256, 256>>>(reinterpret_cast<const float4*>(x));
    cudaFuncSetAttribute(k_gemm, cudaFuncAttributeMaxDynamicSharedMemorySize,
                         (int)SMEM_BYTES);
    dim3 grid(NO / BN, MB / BM);
    k_gemm<<<grid, 512, SMEM_BYTES>>>(out, Wp, Wc);
}

// round 8
// speedup vs baseline: 1.2387x; 1.2387x over previous
#include <cuda_runtime.h>
#include <cuda_fp16.h>
#include <cstdint>
#include <cstddef>

// out = x[1024,65536] @ W2[2048,65536]^T, W2[o,l*32+c]=W_pos[o,l]*W_chan[o,c].
// fp16 operands / fp32 accum via mma.sync.m16n8k16.
// B (=W2) mma fragments are generated IN REGISTERS (rank-1 product: per-lane
// Wc half2 constants x Wp broadcast, 2 HMUL2 per fragment pair) -- B never
// touches shared memory. CTA 128x128x128, 16 warps (warp 32x32), 3-slot
// cp.async for A + Wp.

static constexpr int MB = 1024, NO = 2048, LL = 2048, CC = 32;
static constexpr int KK = LL * CC;                  // 65536

__device__ __half g_xh[(size_t)MB * KK];            // fp16 A

__device__ __forceinline__ uint32_t pk(float a, float b) {
    __half2 h = __floats2half2_rn(a, b);
    return *reinterpret_cast<uint32_t*>(&h);
}

__global__ void k_convert(const float4* __restrict__ x4) {
    int i = blockIdx.x * 256 + threadIdx.x;
    float4 v = x4[i];
    uint2 u; u.x = pk(v.x, v.y); u.y = pk(v.z, v.w);
    reinterpret_cast<uint2*>(g_xh)[i] = u;
}

__device__ __forceinline__ uint32_t smem_u32(const void* p) {
    uint32_t a;
    asm("{ .reg .u64 t; cvta.to.shared.u64 t, %1; cvt.u32.u64 %0, t; }" : "=r"(a) : "l"(p));
    return a;
}
__device__ __forceinline__ void cpa16(uint32_t s, const void* g) {
    asm volatile("cp.async.cg.shared.global [%0], [%1], 16;" :: "r"(s), "l"(g) : "memory");
}
#define CP_COMMIT() asm volatile("cp.async.commit_group;" ::: "memory")
#define CP_WAIT(n)  asm volatile("cp.async.wait_group %0;" :: "n"(n) : "memory")

__device__ __forceinline__ void ldsm4(uint32_t* r, uint32_t a) {
    asm volatile("ldmatrix.sync.aligned.m8n8.x4.shared.b16 {%0,%1,%2,%3}, [%4];"
                 : "=r"(r[0]), "=r"(r[1]), "=r"(r[2]), "=r"(r[3]) : "r"(a));
}
__device__ __forceinline__ void mma16816(float* c, const uint32_t* a,
                                         uint32_t b0, uint32_t b1) {
    asm volatile("mma.sync.aligned.m16n8k16.row.col.f32.f16.f16.f32 "
                 "{%0,%1,%2,%3}, {%4,%5,%6,%7}, {%8,%9}, {%0,%1,%2,%3};"
                 : "+f"(c[0]), "+f"(c[1]), "+f"(c[2]), "+f"(c[3])
                 : "r"(a[0]), "r"(a[1]), "r"(a[2]), "r"(a[3]), "r"(b0), "r"(b1));
}
__device__ __forceinline__ uint32_t hmul2(uint32_t a, uint32_t b) {
    uint32_t d;
    asm("mul.rn.f16x2 %0, %1, %2;" : "=r"(d) : "r"(a), "r"(b));
    return d;
}

static constexpr int BM = 128, BN = 128, KT = 128;
static constexpr int NIT = KK / KT;                 // 512
// smem layout (bytes)
static constexpr uint32_t WP_OFF = 0;               // Wp slots: 3 x 2KB (128 rows x 16B)
static constexpr uint32_t WP_STG = 2048;
static constexpr uint32_t A_OFF  = 6144;            // A slots: 3 x 32KB (256B rows)
static constexpr uint32_t A_STG  = 32768;
static constexpr uint32_t SMEM_BYTES = A_OFF + 3 * A_STG;   // 104448

// 16B-chunk swizzle for 256B rows: XOR within each 128B half
__device__ __forceinline__ uint32_t swz(uint32_t chk, uint32_t row) {
    return (chk & 8u) | ((chk & 7u) ^ (row & 7u));
}

__global__ void __launch_bounds__(512, 1) k_gemm(float* __restrict__ out,
                                                 const float* __restrict__ Wp,
                                                 const float* __restrict__ Wc) {
    extern __shared__ char smem[];
    const uint32_t sb = smem_u32(smem);
    const int t = threadIdx.x;
    const int w = t >> 5, l = t & 31;
    const int m0 = blockIdx.y * BM, n0 = blockIdx.x * BN;
    const int wm = (w >> 2) * 32, wn = (w & 3) * 32;   // 4x4 warp grid, warp 32x32

    // ---- per-lane Wc constants: 4 n-groups x 2 k-parities x 2 half2 ----
    // mma B frag (lane l): n = wn + g*8 + (l>>2); k0 = 16ks + 2(l&3);
    //   b0 = {W2[n,k0], W2[n,k0+1]}, b1 = {W2[n,k0+8], W2[n,k0+9]}
    // c = k mod 32 = p*16 + 2(l&3) + {0,1,8,9},  p = ks&1
    const int c2 = 2 * (l & 3);
    uint32_t wcH[4][2][2];
#pragma unroll
    for (int g = 0; g < 4; ++g) {
        const float* wb = Wc + (size_t)(n0 + wn + g * 8 + (l >> 2)) * CC;
#pragma unroll
        for (int p = 0; p < 2; ++p) {
            const int c = p * 16 + c2;
            wcH[g][p][0] = pk(wb[c], wb[c + 1]);
            wcH[g][p][1] = pk(wb[c + 8], wb[c + 9]);
        }
    }

    // ---- A loader geometry (as R7) ----
    const int ar = t >> 2, aq = t & 3;
    const __half* gA = g_xh + (size_t)(m0 + ar) * KK;
    const uint32_t arx = (uint32_t)(ar & 7);

    auto load_stage = [&](int it, int slot) {
        const uint32_t ab = sb + A_OFF + (uint32_t)slot * A_STG + (uint32_t)ar * 256u;
        const __half* ga = gA + (size_t)it * KT;
#pragma unroll
        for (int i = 0; i < 4; ++i) {
            const uint32_t c = (uint32_t)(aq + 4 * i);
            cpa16(ab + (swz(c, arx) * 16u), ga + c * 8);
        }
        if (t < 128) {
            cpa16(sb + WP_OFF + (uint32_t)slot * WP_STG + (uint32_t)t * 16u,
                  Wp + (size_t)(n0 + t) * LL + (size_t)it * 4);
        }
    };

    float acc[2][4][4];
#pragma unroll
    for (int i = 0; i < 2; ++i)
#pragma unroll
        for (int j = 0; j < 4; ++j)
#pragma unroll
            for (int k = 0; k < 4; ++k) acc[i][j][k] = 0.f;

    load_stage(0, 0); CP_COMMIT();
    load_stage(1, 1); CP_COMMIT();

    // ldmatrix lane geometry for A (verified R3-R7)
    const int arow_i = (l & 7) + ((l >> 3) & 1) * 8, achk_i = (l >> 4);
    const int wp_row0 = (wn + (l >> 2)) * 16;       // Wp smem row offset, g=0

    uint32_t af[2][2][4];
    int slotC = 0, slotG = 1, slotP = 2;
    for (int it = 0; it < NIT; ++it) {
        CP_WAIT(0);
        __syncthreads();      // A[it], Wp[it] (and earlier) published

        if (it + 2 < NIT) { load_stage(it + 2, slotP); CP_COMMIT(); }

        const uint32_t ast = sb + A_OFF + (uint32_t)slotC * A_STG;

        // Wp values for this k-slice: 4 n-groups x 4 l-positions
        float wpf[4][4];
        {
            const uint32_t wps = sb + WP_OFF + (uint32_t)slotC * WP_STG;
#pragma unroll
            for (int g = 0; g < 4; ++g) {
                float4 v;
                asm volatile("ld.shared.v4.f32 {%0,%1,%2,%3}, [%4];"
                             : "=f"(v.x), "=f"(v.y), "=f"(v.z), "=f"(v.w)
                             : "r"(wps + (uint32_t)(wp_row0 + g * 128)));
                wpf[g][0] = v.x; wpf[g][1] = v.y; wpf[g][2] = v.z; wpf[g][3] = v.w;
            }
        }

        auto load_afrags = [&](int ks, int buf) {
#pragma unroll
            for (int mi = 0; mi < 2; ++mi) {
                const uint32_t row = (uint32_t)(wm + mi * 16 + arow_i);
                const uint32_t chk = (uint32_t)(achk_i + ks * 2);
                ldsm4(af[buf][mi], ast + row * 256u + swz(chk, row) * 16u);
            }
        };

        load_afrags(0, 0);
        uint32_t wph2[4];
#pragma unroll
        for (int ks = 0; ks < KT / 16; ++ks) {
            if (ks + 1 < KT / 16) load_afrags(ks + 1, (ks + 1) & 1);
            const int bu = ks & 1, p = ks & 1, lp = ks >> 1;
#pragma unroll
            for (int g = 0; g < 4; ++g) {
                if (p == 0) wph2[g] = pk(wpf[g][lp], wpf[g][lp]);
                const uint32_t b0 = hmul2(wph2[g], wcH[g][p][0]);
                const uint32_t b1 = hmul2(wph2[g], wcH[g][p][1]);
                mma16816(acc[0][g], af[bu][0], b0, b1);
                mma16816(acc[1][g], af[bu][1], b0, b1);
            }
        }

        const int tmp = slotC;
        slotC = slotG; slotG = slotP; slotP = tmp;
    }

#pragma unroll
    for (int mi = 0; mi < 2; ++mi) {
        const int row = m0 + wm + mi * 16 + (l >> 2);
#pragma unroll
        for (int g = 0; g < 4; ++g) {
            const int col = n0 + wn + g * 8 + (l & 3) * 2;
            float2 lo; lo.x = acc[mi][g][0]; lo.y = acc[mi][g][1];
            float2 hi; hi.x = acc[mi][g][2]; hi.y = acc[mi][g][3];
            *reinterpret_cast<float2*>(out + (size_t)row * NO + col) = lo;
            *reinterpret_cast<float2*>(out + (size_t)(row + 8) * NO + col) = hi;
        }
    }
}

extern "C" void kernel_launch(void* const* d_in, const int* in_sizes, int n_in,
                              void* d_out, int out_size) {
    (void)in_sizes; (void)n_in; (void)out_size;
    const float* x  = (const float*)d_in[0];
    const float* Wp = (const float*)d_in[1];
    const float* Wc = (const float*)d_in[2];
    float* out = (float*)d_out;

    k_convert<<<(MB * (KK / 4)) / 256, 256>>>(reinterpret_cast<const float4*>(x));
    cudaFuncSetAttribute(k_gemm, cudaFuncAttributeMaxDynamicSharedMemorySize,
                         (int)SMEM_BYTES);
    dim3 grid(NO / BN, MB / BM);
    k_gemm<<<grid, 512, SMEM_BYTES>>>(out, Wp, Wc);
}